// round 7
// baseline (speedup 1.0000x reference)
#include <cuda_runtime.h>
#include <cuda_fp16.h>
#include <cstdint>

#define B_    16
#define CIN   256
#define COUT  512
#define HB2   129   // blurred H/W

// Blurred intermediate, channel-blocked NHWC: [b][c/8][129][129][8] fp16.
static __device__ __align__(128) __half g_x[(size_t)B_ * 32 * HB2 * HB2 * 8];
static __device__ __align__(128) __half g_w[9 * COUT * CIN];   // [tap][oc][cin]

// ---------------------------------------------------------------------------
__device__ __forceinline__ uint32_t smem_u32(const void* p) {
    uint32_t a;
    asm("{ .reg .u64 t; cvta.to.shared.u64 t, %1; cvt.u32.u64 %0, t; }" : "=r"(a) : "l"(p));
    return a;
}
__device__ __forceinline__ void cp16(uint32_t d, const void* s) {
    asm volatile("cp.async.cg.shared.global [%0], [%1], 16;" :: "r"(d), "l"(s));
}
__device__ __forceinline__ void cp_commit() {
    asm volatile("cp.async.commit_group;" ::: "memory");
}
__device__ __forceinline__ void cp_wait2() {
    asm volatile("cp.async.wait_group 2;" ::: "memory");
}
__device__ __forceinline__ void ldsm4(uint32_t* r, uint32_t a) {
    asm volatile("ldmatrix.sync.aligned.m8n8.x4.shared.b16 {%0,%1,%2,%3}, [%4];"
                 : "=r"(r[0]), "=r"(r[1]), "=r"(r[2]), "=r"(r[3]) : "r"(a));
}
__device__ __forceinline__ void mma16816(float* c, const uint32_t* a, const uint32_t* b) {
    asm volatile(
        "mma.sync.aligned.m16n8k16.row.col.f32.f16.f16.f32 "
        "{%0,%1,%2,%3}, {%4,%5,%6,%7}, {%8,%9}, {%0,%1,%2,%3};"
        : "+f"(c[0]), "+f"(c[1]), "+f"(c[2]), "+f"(c[3])
        : "r"(a[0]), "r"(a[1]), "r"(a[2]), "r"(a[3]), "r"(b[0]), "r"(b[1]));
}

// ---------------------------------------------------------------------------
// Stage 1: separable 4x4 blur, NCHW fp32 -> channel-blocked NHWC fp16.
// Warp = one channel, sweeping a row SEGMENT (2 segments/image -> 2x grid).
// H-pass in registers via shuffles; V-pass via 4-deep register ring.
// Flush: stage[8 rows][129 w][8 c] -> 16B per w, consecutive w contiguous
// in the blocked layout => fully coalesced stores.
// Block: 8 warps = 8 channels = one channel block. Grid: 16b x 32cb x 2seg.
// ---------------------------------------------------------------------------
__global__ void __launch_bounds__(256) blur_kernel(const float* __restrict__ x) {
    __shared__ __half stage[8][132][8];
    const int seg = blockIdx.x & 1;
    const int cb  = (blockIdx.x >> 1) & 31;
    const int b   = blockIdx.x >> 6;
    const int lane = threadIdx.x, c = threadIdx.y;
    const float* xc = x + ((size_t)(b * CIN + cb * 8 + c)) * (128 * 128);

    const int oh0 = seg * 65;
    const int ohN = seg ? 64 : 65;

    float ring[4][4], ringE[4];
#pragma unroll
    for (int j = 0; j < 4; j++) {
        ringE[j] = 0.f;
#pragma unroll
        for (int k = 0; k < 4; k++) ring[j][k] = 0.f;
    }

    for (int r = oh0 - 2; r <= oh0 + ohN; r++) {
        const int u = (r + 4) & 3;
        float4 q = make_float4(0.f, 0.f, 0.f, 0.f);
        if ((unsigned)r < 128u) q = *(const float4*)(xc + r * 128 + lane * 4);
        float pz = __shfl_up_sync(0xffffffffu, q.z, 1);
        float pw = __shfl_up_sync(0xffffffffu, q.w, 1);
        float nx = __shfl_down_sync(0xffffffffu, q.x, 1);
        if (lane == 0)  { pz = 0.f; pw = 0.f; }
        if (lane == 31) { nx = 0.f; }
        ring[u][0] = 0.125f * (pz + q.y)  + 0.375f * (pw + q.x);
        ring[u][1] = 0.125f * (pw + q.z)  + 0.375f * (q.x + q.y);
        ring[u][2] = 0.125f * (q.x + q.w) + 0.375f * (q.y + q.z);
        ring[u][3] = 0.125f * (q.y + nx)  + 0.375f * (q.z + q.w);
        ringE[u]   = 0.125f * q.z + 0.375f * q.w;   // w=128 (lane 31)

        const int oh = r - 1;
        if (oh >= oh0) {
            const int s0 = (r + 1) & 3, s1 = (r + 2) & 3, s2 = (r + 3) & 3, s3 = u;
            const int ohl = oh - oh0;
            const int slot = ohl & 7;
#pragma unroll
            for (int k = 0; k < 4; k++) {
                float o = 0.125f * (ring[s0][k] + ring[s3][k])
                        + 0.375f * (ring[s1][k] + ring[s2][k]);
                stage[slot][4 * lane + k][c] = __float2half_rn(o);
            }
            if (lane == 31) {
                float oE = 0.125f * (ringE[s0] + ringE[s3])
                         + 0.375f * (ringE[s1] + ringE[s2]);
                stage[slot][128][c] = __float2half_rn(oE);
            }
            if ((ohl & 7) == 7 || ohl == ohN - 1) {
                __syncthreads();
                const int fbase = ohl & ~7;
                if (fbase + c <= ohl) {          // threadIdx.y = flush row
                    const int oh2 = oh0 + fbase + c;
                    size_t gb = (((size_t)(b * 32 + cb) * HB2 + oh2) * HB2) * 8;
                    for (int w = lane; w < 129; w += 32)
                        *(uint4*)(g_x + gb + (size_t)w * 8) =
                            *(const uint4*)&stage[c][w][0];
                }
                __syncthreads();
            }
        }
    }
}

// ---------------------------------------------------------------------------
// Weight prep: w[3][3][CIN][COUT] fp32 -> g_w[tap][COUT][CIN] fp16, * 1/48.
// ---------------------------------------------------------------------------
__global__ void __launch_bounds__(256) wprep_kernel(const float* __restrict__ w) {
    __shared__ float t[32][33];
    const int tap = blockIdx.z, o0 = blockIdx.x * 32, cb0 = blockIdx.y * 32;
    const int tx = threadIdx.x, ty = threadIdx.y;
    const float sc = 1.0f / 48.0f;
    for (int r = ty; r < 32; r += 8)
        t[r][tx] = w[((size_t)tap * CIN + cb0 + r) * COUT + o0 + tx] * sc;
    __syncthreads();
    for (int r = ty; r < 32; r += 8)
        g_w[((size_t)tap * COUT + o0 + r) * CIN + cb0 + tx] = __float2half_rn(t[tx][r]);
}

// ---------------------------------------------------------------------------
// Stage 2: implicit GEMM via mma.sync (fp16 in, fp32 accum).
// CTA: 256 thr = 8 warps (2m x 4n), tile M=128 px x N=256 oc, warp 64x64.
// K=2304 in 72 chunks of 32. 4-stage cp.async ring, wait_group 2, one
// __syncthreads per chunk. Per 16-k-step: 8 ldsm4 + 32 mma (ratio 4).
// ---------------------------------------------------------------------------
#define TSTR  40                    // fp16 elements per smem row
#define ASZ   10240                 // A stage: 128 rows * 80B
#define BSZ   20480                 // B stage: 256 rows * 80B
#define STGB  (ASZ + BSZ)           // 30720
#define SMEM_BYTES (4 * STGB)       // 122880

__global__ void __launch_bounds__(256) conv_mma_kernel(
    const float* __restrict__ bias, float* __restrict__ out)
{
    extern __shared__ char smem[];
    const uint32_t sA = smem_u32(smem);
    const int tid = threadIdx.x, lane = tid & 31, wid = tid >> 5;
    const int hb  = blockIdx.x * 2;     // 2 output rows per CTA
    const int oc0 = blockIdx.y * 256;
    const int b   = blockIdx.z;
    const int wm  = (wid & 1) * 64;     // warp m offset
    const int wn  = (wid >> 1) * 64;    // warp n offset (0..192)

    float acc[4][8][4];
#pragma unroll
    for (int i = 0; i < 4; i++)
#pragma unroll
        for (int j = 0; j < 8; j++)
#pragma unroll
            for (int k = 0; k < 4; k++) acc[i][j][k] = 0.f;

    // A: thread -> row ar (0..127) + k-half hk. B: thread -> row tid (full 64B).
    const int ar = tid >> 1, hk = tid & 1;
    const int oh = hb + (ar >> 6), ow = ar & 63;

#define ISSUE_LOADS(chunk, stg)                                                  \
    {                                                                            \
        const int tap = (chunk) >> 3, c0 = ((chunk) & 7) << 5;                   \
        const int kh = tap / 3, kw = tap - kh * 3;                               \
        const int cb0 = (c0 >> 3) + hk * 2;                                      \
        const size_t a0 = ((((size_t)(b * 32 + cb0)) * HB2 + (2 * oh + kh))      \
                           * HB2 + (2 * ow + kw)) * 8;                           \
        const uint32_t d = sA + (stg) * STGB + ar * 80 + hk * 32;                \
        cp16(d, g_x + a0);                                                       \
        cp16(d + 16, g_x + a0 + (size_t)HB2 * HB2 * 8);                          \
        const size_t bo = ((size_t)(tap * COUT + oc0 + tid)) * CIN + c0;         \
        const uint32_t e = sA + (stg) * STGB + ASZ + tid * 80;                   \
        cp16(e, g_w + bo);           cp16(e + 16, g_w + bo + 8);                 \
        cp16(e + 32, g_w + bo + 16); cp16(e + 48, g_w + bo + 24);                \
    }

    ISSUE_LOADS(0, 0); cp_commit();
    ISSUE_LOADS(1, 1); cp_commit();
    ISSUE_LOADS(2, 2); cp_commit();

    for (int i = 0; i < 72; i++) {
        cp_wait2();
        __syncthreads();
        const uint32_t base = sA + (i & 3) * STGB;

#pragma unroll
        for (int ks = 0; ks < 32; ks += 16) {
            uint32_t af[4][4], bf[4][4];
#pragma unroll
            for (int mt = 0; mt < 4; mt++) {
                uint32_t a = base + ((wm + mt * 16 + (lane & 15)) * TSTR
                                     + ks + ((lane & 16) >> 1)) * 2;
                ldsm4(af[mt], a);
            }
#pragma unroll
            for (int bt = 0; bt < 4; bt++) {
                uint32_t a = base + ASZ
                           + ((wn + bt * 16 + (lane & 7) + ((lane & 16) >> 1)) * TSTR
                              + ks + (lane & 8)) * 2;
                ldsm4(bf[bt], a);
            }
#pragma unroll
            for (int mt = 0; mt < 4; mt++)
#pragma unroll
                for (int bt = 0; bt < 4; bt++)
#pragma unroll
                    for (int h = 0; h < 2; h++)
                        mma16816(acc[mt][bt * 2 + h], af[mt], &bf[bt][2 * h]);
        }
        if (i + 3 < 72) ISSUE_LOADS(i + 3, (i + 3) & 3);
        cp_commit();
    }

    // Epilogue: two 128-oc halves staged through smem -> coalesced writes.
    float* so = (float*)smem;           // 128 x 132 floats = 67.6KB
    const float gsc = 1.41421356237309515f;
#pragma unroll 1
    for (int half = 0; half < 2; half++) {
        __syncthreads();
        if ((wn >> 7) == half) {
            const int wnl = wn & 127;
#pragma unroll
            for (int mt = 0; mt < 4; mt++)
#pragma unroll
                for (int nt = 0; nt < 8; nt++)
#pragma unroll
                    for (int k = 0; k < 4; k++) {
                        int px  = wm + mt * 16 + (lane >> 2) + ((k & 2) ? 8 : 0);
                        int ocl = wnl + nt * 8 + (lane & 3) * 2 + (k & 1);
                        so[ocl * 132 + px] = acc[mt][nt][k];
                    }
        }
        __syncthreads();
        const int ocl = tid >> 1, pxb = (tid & 1) * 64;
        const int oc = oc0 + half * 128 + ocl;
        const float bv = bias[oc];
        float* dst = out + (((size_t)(b * COUT + oc) * 64) + hb + (tid & 1)) * 64;
#pragma unroll
        for (int j = 0; j < 64; j += 4) {
            float4 v = *(const float4*)(so + ocl * 132 + pxb + j);
            v.x = ((v.x + bv) > 0.f ? (v.x + bv) : 0.2f * (v.x + bv)) * gsc;
            v.y = ((v.y + bv) > 0.f ? (v.y + bv) : 0.2f * (v.y + bv)) * gsc;
            v.z = ((v.z + bv) > 0.f ? (v.z + bv) : 0.2f * (v.z + bv)) * gsc;
            v.w = ((v.w + bv) > 0.f ? (v.w + bv) : 0.2f * (v.w + bv)) * gsc;
            *(float4*)(dst + j) = v;
        }
    }
}

// ---------------------------------------------------------------------------
extern "C" void kernel_launch(void* const* d_in, const int* in_sizes, int n_in,
                              void* d_out, int out_size) {
    const float* x    = (const float*)d_in[0];   // [16,256,128,128]
    const float* w    = (const float*)d_in[1];   // [3,3,256,512]
    const float* bias = (const float*)d_in[2];   // [512]
    float* out = (float*)d_out;                  // [16,512,64,64]

    cudaFuncSetAttribute(conv_mma_kernel,
                         cudaFuncAttributeMaxDynamicSharedMemorySize, SMEM_BYTES);

    blur_kernel<<<1024, dim3(32, 8)>>>(x);
    wprep_kernel<<<dim3(16, 8, 9), dim3(32, 8)>>>(w);
    conv_mma_kernel<<<dim3(32, 2, B_), 256, SMEM_BYTES>>>(bias, out);
}

// round 8
// speedup vs baseline: 1.0659x; 1.0659x over previous
#include <cuda_runtime.h>
#include <cuda_fp16.h>
#include <cstdint>

#define B_    16
#define CIN   256
#define COUT  512
#define HB2   129   // blurred H/W

// Blurred intermediate, channel-blocked NHWC: [b][c/8][129][129][8] fp16.
static __device__ __align__(128) __half g_x[(size_t)B_ * 32 * HB2 * HB2 * 8];
static __device__ __align__(128) __half g_w[9 * COUT * CIN];   // [tap][oc][cin]

#define XBLK ((size_t)HB2 * HB2 * 8)   // halves per channel-block image

// ---------------------------------------------------------------------------
__device__ __forceinline__ uint32_t smem_u32(const void* p) {
    uint32_t a;
    asm("{ .reg .u64 t; cvta.to.shared.u64 t, %1; cvt.u32.u64 %0, t; }" : "=r"(a) : "l"(p));
    return a;
}
__device__ __forceinline__ void cp16(uint32_t d, const void* s) {
    asm volatile("cp.async.cg.shared.global [%0], [%1], 16;" :: "r"(d), "l"(s));
}
__device__ __forceinline__ void cp_commit() {
    asm volatile("cp.async.commit_group;" ::: "memory");
}
__device__ __forceinline__ void cp_wait2() {
    asm volatile("cp.async.wait_group 2;" ::: "memory");
}
__device__ __forceinline__ void ldsm4(uint32_t* r, uint32_t a) {
    asm volatile("ldmatrix.sync.aligned.m8n8.x4.shared.b16 {%0,%1,%2,%3}, [%4];"
                 : "=r"(r[0]), "=r"(r[1]), "=r"(r[2]), "=r"(r[3]) : "r"(a));
}
__device__ __forceinline__ void ldsm4t(uint32_t* r, uint32_t a) {
    asm volatile("ldmatrix.sync.aligned.m8n8.x4.trans.shared.b16 {%0,%1,%2,%3}, [%4];"
                 : "=r"(r[0]), "=r"(r[1]), "=r"(r[2]), "=r"(r[3]) : "r"(a));
}
__device__ __forceinline__ void mma16816(float* c, const uint32_t* a, const uint32_t* b) {
    asm volatile(
        "mma.sync.aligned.m16n8k16.row.col.f32.f16.f16.f32 "
        "{%0,%1,%2,%3}, {%4,%5,%6,%7}, {%8,%9}, {%0,%1,%2,%3};"
        : "+f"(c[0]), "+f"(c[1]), "+f"(c[2]), "+f"(c[3])
        : "r"(a[0]), "r"(a[1]), "r"(a[2]), "r"(a[3]), "r"(b[0]), "r"(b[1]));
}

// ---------------------------------------------------------------------------
// Stage 1: separable 4x4 blur, NCHW fp32 -> channel-blocked NHWC fp16.
// Warp = one channel, sweeping a row segment. H-pass via shuffles, V-pass
// via 4-deep register ring. Stage smem is CHANNEL-MAJOR [slot][c][w136]:
// V-pass stores are 2xSTS.32 at 8B lane stride (2-way conflict only).
// Flush transposes with ldmatrix.x4.trans (conflict-free: 272B row stride)
// and writes 4B words forming 128B-contiguous global stores.
// ---------------------------------------------------------------------------
__global__ void __launch_bounds__(256) blur_kernel(const float* __restrict__ x) {
    __shared__ __align__(16) __half stage[8][8][136];   // 17408 B
    const int seg = blockIdx.x & 1;
    const int cb  = (blockIdx.x >> 1) & 31;
    const int b   = blockIdx.x >> 6;
    const int lane = threadIdx.x, c = threadIdx.y, wid = threadIdx.y;
    const float* xc = x + ((size_t)(b * CIN + cb * 8 + c)) * (128 * 128);

    const int oh0 = seg * 65;
    const int ohN = seg ? 64 : 65;

    float ring[4][4], ringE[4];
#pragma unroll
    for (int j = 0; j < 4; j++) {
        ringE[j] = 0.f;
#pragma unroll
        for (int k = 0; k < 4; k++) ring[j][k] = 0.f;
    }

    for (int r = oh0 - 2; r <= oh0 + ohN; r++) {
        const int u = (r + 4) & 3;
        float4 q = make_float4(0.f, 0.f, 0.f, 0.f);
        if ((unsigned)r < 128u) q = *(const float4*)(xc + r * 128 + lane * 4);
        float pz = __shfl_up_sync(0xffffffffu, q.z, 1);
        float pw = __shfl_up_sync(0xffffffffu, q.w, 1);
        float nx = __shfl_down_sync(0xffffffffu, q.x, 1);
        if (lane == 0)  { pz = 0.f; pw = 0.f; }
        if (lane == 31) { nx = 0.f; }
        ring[u][0] = 0.125f * (pz + q.y)  + 0.375f * (pw + q.x);
        ring[u][1] = 0.125f * (pw + q.z)  + 0.375f * (q.x + q.y);
        ring[u][2] = 0.125f * (q.x + q.w) + 0.375f * (q.y + q.z);
        ring[u][3] = 0.125f * (q.y + nx)  + 0.375f * (q.z + q.w);
        ringE[u]   = 0.125f * q.z + 0.375f * q.w;   // w=128 (lane 31)

        const int oh = r - 1;
        if (oh >= oh0) {
            const int s0 = (r + 1) & 3, s1 = (r + 2) & 3, s2 = (r + 3) & 3, s3 = u;
            const int ohl = oh - oh0;
            const int slot = ohl & 7;
            float o0 = 0.125f * (ring[s0][0] + ring[s3][0]) + 0.375f * (ring[s1][0] + ring[s2][0]);
            float o1 = 0.125f * (ring[s0][1] + ring[s3][1]) + 0.375f * (ring[s1][1] + ring[s2][1]);
            float o2 = 0.125f * (ring[s0][2] + ring[s3][2]) + 0.375f * (ring[s1][2] + ring[s2][2]);
            float o3 = 0.125f * (ring[s0][3] + ring[s3][3]) + 0.375f * (ring[s1][3] + ring[s2][3]);
            __half2* sp = (__half2*)&stage[slot][c][4 * lane];
            sp[0] = __floats2half2_rn(o0, o1);
            sp[1] = __floats2half2_rn(o2, o3);
            if (lane == 31) {
                float oE = 0.125f * (ringE[s0] + ringE[s3])
                         + 0.375f * (ringE[s1] + ringE[s2]);
                stage[slot][c][128] = __float2half_rn(oE);
            }
            if ((ohl & 7) == 7 || ohl == ohN - 1) {
                __syncthreads();
                const int fbase = ohl & ~7;
                if (fbase + wid <= ohl) {
                    const int oh2 = oh0 + fbase + wid;
                    __half* gb = g_x + (((size_t)(b * 32 + cb)) * HB2 + oh2) * HB2 * 8;
                    // 4 x ldmatrix.x4.trans: tiles = w-chunks of 8.
                    // Lane l supplies row (channel l&7) of tile l>>3.
#pragma unroll
                    for (int t4 = 0; t4 < 4; t4++) {
                        const int w0 = 32 * t4;
                        uint32_t addr = smem_u32(&stage[wid][lane & 7][w0 + 8 * (lane >> 3)]);
                        uint32_t rg[4];
                        ldsm4t(rg, addr);
                        // Lane l holds channels {2*(l&3), +1} at w = w0+8k+(l>>2).
                        uint32_t* gw = (uint32_t*)gb;
#pragma unroll
                        for (int k = 0; k < 4; k++)
                            gw[(w0 + 8 * k + (lane >> 2)) * 4 + (lane & 3)] = rg[k];
                    }
                    if (lane < 8)   // w = 128 edge: one 2B store per channel
                        gb[128 * 8 + lane] = stage[wid][lane][128];
                }
                __syncthreads();
            }
        }
    }
}

// ---------------------------------------------------------------------------
// Weight prep: w[3][3][CIN][COUT] fp32 -> g_w[tap][COUT][CIN] fp16, * 1/48.
// ---------------------------------------------------------------------------
__global__ void __launch_bounds__(256) wprep_kernel(const float* __restrict__ w) {
    __shared__ float t[32][33];
    const int tap = blockIdx.z, o0 = blockIdx.x * 32, cb0 = blockIdx.y * 32;
    const int tx = threadIdx.x, ty = threadIdx.y;
    const float sc = 1.0f / 48.0f;
    for (int r = ty; r < 32; r += 8)
        t[r][tx] = w[((size_t)tap * CIN + cb0 + r) * COUT + o0 + tx] * sc;
    __syncthreads();
    for (int r = ty; r < 32; r += 8)
        g_w[((size_t)tap * COUT + o0 + r) * CIN + cb0 + tx] = __float2half_rn(t[tx][r]);
}

// ---------------------------------------------------------------------------
// Stage 2: implicit GEMM via mma.sync (fp16 in, fp32 accum) — R5 config.
// CTA: 256 thr, tile M=128 px x N=128 oc. K=2304 in 72 chunks of 32.
// 4-stage cp.async ring, one __syncthreads per stage, wait_group 2.
// SMEM stride 40 fp16; 81920 B total -> 2 CTAs/SM.
// ---------------------------------------------------------------------------
#define TSTR  40                    // fp16 elements per smem row
#define STGB  20480                 // (128 A-rows + 128 B-rows) * 80B
#define SMEM_BYTES (4 * STGB)       // 81920

__global__ void __launch_bounds__(256, 2) conv_mma_kernel(
    const float* __restrict__ bias, float* __restrict__ out)
{
    extern __shared__ char smem[];
    const uint32_t sA = smem_u32(smem);
    const int tid = threadIdx.x, lane = tid & 31, wid = tid >> 5;
    const int hb  = blockIdx.x * 2;     // 2 output rows per CTA
    const int oc0 = blockIdx.y * 128;
    const int b   = blockIdx.z;
    const int wm  = (wid & 3) * 32;     // warp m offset
    const int wn  = (wid >> 2) * 64;    // warp n offset

    float acc[2][8][4];
#pragma unroll
    for (int i = 0; i < 2; i++)
#pragma unroll
        for (int j = 0; j < 8; j++)
#pragma unroll
            for (int k = 0; k < 4; k++) acc[i][j][k] = 0.f;

    // Load mapping: thread -> row r (0..127), k-half hk (16 fp16 = 2 blocks).
    const int r  = tid >> 1;
    const int hk = tid & 1;
    const int oh = hb + (r >> 6), ow = r & 63;

#define ISSUE_LOADS(chunk, stg)                                                  \
    {                                                                            \
        const int tap = (chunk) >> 3, c0 = ((chunk) & 7) << 5;                   \
        const int kh = tap / 3, kw = tap - kh * 3;                               \
        const int cbb = (c0 >> 3) + hk * 2;                                      \
        const size_t a0 = ((((size_t)(b * 32 + cbb)) * HB2 + (2 * oh + kh))      \
                           * HB2 + (2 * ow + kw)) * 8;                           \
        const size_t bo = ((size_t)(tap * COUT + oc0 + r)) * CIN + c0 + hk * 16; \
        const uint32_t d = sA + (stg) * STGB + r * 80 + hk * 32;                 \
        cp16(d, g_x + a0);              cp16(d + 16, g_x + a0 + XBLK);           \
        const uint32_t e = d + 10240;                                            \
        cp16(e, g_w + bo);              cp16(e + 16, g_w + bo + 8);              \
    }

    ISSUE_LOADS(0, 0); cp_commit();
    ISSUE_LOADS(1, 1); cp_commit();
    ISSUE_LOADS(2, 2); cp_commit();

    for (int i = 0; i < 72; i++) {
        cp_wait2();
        __syncthreads();
        const uint32_t base = sA + (i & 3) * STGB;

#pragma unroll
        for (int ks = 0; ks < 32; ks += 16) {
            uint32_t af[2][4], bf[4][4];
#pragma unroll
            for (int mt = 0; mt < 2; mt++) {
                uint32_t a = base + ((wm + mt * 16 + (lane & 15)) * TSTR
                                     + ks + ((lane & 16) >> 1)) * 2;
                ldsm4(af[mt], a);
            }
#pragma unroll
            for (int bt = 0; bt < 4; bt++) {
                uint32_t a = base + 10240
                           + ((wn + bt * 16 + (lane & 7) + ((lane & 16) >> 1)) * TSTR
                              + ks + (lane & 8)) * 2;
                ldsm4(bf[bt], a);
            }
#pragma unroll
            for (int mt = 0; mt < 2; mt++)
#pragma unroll
                for (int bt = 0; bt < 4; bt++)
#pragma unroll
                    for (int h = 0; h < 2; h++)
                        mma16816(acc[mt][bt * 2 + h], af[mt], &bf[bt][2 * h]);
        }
        if (i + 3 < 72) ISSUE_LOADS(i + 3, (i + 3) & 3);
        cp_commit();
    }
    __syncthreads();   // all warps done reading stages before smem reuse

    // Epilogue: stage [oc_local][px] fp32 in smem, then coalesced writes.
    float* so = (float*)smem;           // 128 x 132 floats = 67.6KB <= 80KB
#pragma unroll
    for (int mt = 0; mt < 2; mt++)
#pragma unroll
        for (int nt = 0; nt < 8; nt++)
#pragma unroll
            for (int k = 0; k < 4; k++) {
                int px  = wm + mt * 16 + (lane >> 2) + ((k & 2) ? 8 : 0);
                int ocl = wn + nt * 8 + (lane & 3) * 2 + (k & 1);
                so[ocl * 132 + px] = acc[mt][nt][k];
            }
    __syncthreads();

    const int ocl = tid >> 1, pxb = (tid & 1) * 64;
    const float bv = bias[oc0 + ocl];
    const float gsc = 1.41421356237309515f;
    float* dst = out + (((size_t)(b * COUT + oc0 + ocl) * 64) + hb + (tid & 1)) * 64;
#pragma unroll
    for (int j = 0; j < 64; j += 4) {
        float4 v = *(const float4*)(so + ocl * 132 + pxb + j);
        v.x = ((v.x + bv) > 0.f ? (v.x + bv) : 0.2f * (v.x + bv)) * gsc;
        v.y = ((v.y + bv) > 0.f ? (v.y + bv) : 0.2f * (v.y + bv)) * gsc;
        v.z = ((v.z + bv) > 0.f ? (v.z + bv) : 0.2f * (v.z + bv)) * gsc;
        v.w = ((v.w + bv) > 0.f ? (v.w + bv) : 0.2f * (v.w + bv)) * gsc;
        *(float4*)(dst + j) = v;
    }
}

// ---------------------------------------------------------------------------
extern "C" void kernel_launch(void* const* d_in, const int* in_sizes, int n_in,
                              void* d_out, int out_size) {
    const float* x    = (const float*)d_in[0];   // [16,256,128,128]
    const float* w    = (const float*)d_in[1];   // [3,3,256,512]
    const float* bias = (const float*)d_in[2];   // [512]
    float* out = (float*)d_out;                  // [16,512,64,64]

    cudaFuncSetAttribute(conv_mma_kernel,
                         cudaFuncAttributeMaxDynamicSharedMemorySize, SMEM_BYTES);

    blur_kernel<<<1024, dim3(32, 8)>>>(x);
    wprep_kernel<<<dim3(16, 8, 9), dim3(32, 8)>>>(w);
    conv_mma_kernel<<<dim3(32, 4, B_), 256, SMEM_BYTES>>>(bias, out);
}

// round 9
// speedup vs baseline: 1.2205x; 1.1451x over previous
#include <cuda_runtime.h>
#include <cuda_fp16.h>
#include <cstdint>

#define B_    16
#define CIN   256
#define COUT  512
#define HB2   129   // blurred H/W

// Blurred intermediate, parity-split channel-blocked:
//   g_xE[b][cb][h][w2][8c] holds w = 2*w2   (w2 = 0..64)
//   g_xO[b][cb][h][w2][8c] holds w = 2*w2+1 (w2 = 0..63; 64 unused)
#define PBLK ((size_t)HB2 * 65 * 8)   // halves per channel-block per plane
static __device__ __align__(128) __half g_xE[(size_t)B_ * 32 * PBLK];
static __device__ __align__(128) __half g_xO[(size_t)B_ * 32 * PBLK];
static __device__ __align__(128) __half g_w[9 * COUT * CIN];   // [tap][oc][cin]

// ---------------------------------------------------------------------------
__device__ __forceinline__ uint32_t smem_u32(const void* p) {
    uint32_t a;
    asm("{ .reg .u64 t; cvta.to.shared.u64 t, %1; cvt.u32.u64 %0, t; }" : "=r"(a) : "l"(p));
    return a;
}
__device__ __forceinline__ void cp16(uint32_t d, const void* s) {
    asm volatile("cp.async.cg.shared.global [%0], [%1], 16;" :: "r"(d), "l"(s));
}
__device__ __forceinline__ void cp_commit() {
    asm volatile("cp.async.commit_group;" ::: "memory");
}
__device__ __forceinline__ void cp_wait3() {
    asm volatile("cp.async.wait_group 3;" ::: "memory");
}
__device__ __forceinline__ void ldsm4(uint32_t* r, uint32_t a) {
    asm volatile("ldmatrix.sync.aligned.m8n8.x4.shared.b16 {%0,%1,%2,%3}, [%4];"
                 : "=r"(r[0]), "=r"(r[1]), "=r"(r[2]), "=r"(r[3]) : "r"(a));
}
__device__ __forceinline__ void ldsm4t(uint32_t* r, uint32_t a) {
    asm volatile("ldmatrix.sync.aligned.m8n8.x4.trans.shared.b16 {%0,%1,%2,%3}, [%4];"
                 : "=r"(r[0]), "=r"(r[1]), "=r"(r[2]), "=r"(r[3]) : "r"(a));
}
__device__ __forceinline__ void mma16816(float* c, const uint32_t* a, const uint32_t* b) {
    asm volatile(
        "mma.sync.aligned.m16n8k16.row.col.f32.f16.f16.f32 "
        "{%0,%1,%2,%3}, {%4,%5,%6,%7}, {%8,%9}, {%0,%1,%2,%3};"
        : "+f"(c[0]), "+f"(c[1]), "+f"(c[2]), "+f"(c[3])
        : "r"(a[0]), "r"(a[1]), "r"(a[2]), "r"(a[3]), "r"(b[0]), "r"(b[1]));
}

// ---------------------------------------------------------------------------
// Stage 1: separable 4x4 blur, NCHW fp32 -> parity-split blocked fp16.
// Warp = one channel over a row segment. STATIC register ring (unroll 4).
// Stage smem channel-major per parity: [slot][c][w2 pad 72]; V-pass emits
// half2 at 4B lane stride (conflict-free). Flush: ldmatrix.x4.trans per
// plane (conflict-free @144B row stride), stores 128B-contiguous runs.
// ---------------------------------------------------------------------------
__global__ void __launch_bounds__(256) blur_kernel(const float* __restrict__ x) {
    __shared__ __align__(16) __half stE[8][8][72];   // 9216 B
    __shared__ __align__(16) __half stO[8][8][72];   // 9216 B
    const int seg = blockIdx.x & 1;
    const int cb  = (blockIdx.x >> 1) & 31;
    const int b   = blockIdx.x >> 6;
    const int lane = threadIdx.x, c = threadIdx.y;
    const float* xc = x + ((size_t)(b * CIN + cb * 8 + c)) * (128 * 128);

    const int oh0 = seg * 65;
    const int ohN = seg ? 64 : 65;

    float ring[4][4], ringE[4];
#pragma unroll
    for (int j = 0; j < 4; j++) {
        ringE[j] = 0.f;
#pragma unroll
        for (int k = 0; k < 4; k++) ring[j][k] = 0.f;
    }

    for (int it = 0; it < 17; it++) {
#pragma unroll
        for (int u = 0; u < 4; u++) {
            const int r = oh0 - 2 + 4 * it + u;          // u static
            float4 q = make_float4(0.f, 0.f, 0.f, 0.f);
            if ((unsigned)r < 128u) q = *(const float4*)(xc + r * 128 + lane * 4);
            float pz = __shfl_up_sync(0xffffffffu, q.z, 1);
            float pw = __shfl_up_sync(0xffffffffu, q.w, 1);
            float nx = __shfl_down_sync(0xffffffffu, q.x, 1);
            if (lane == 0)  { pz = 0.f; pw = 0.f; }
            if (lane == 31) { nx = 0.f; }
            const int u0 = (u + 2) & 3;                  // slot for row r (static)
            ring[u0][0] = 0.125f * (pz + q.y)  + 0.375f * (pw + q.x);
            ring[u0][1] = 0.125f * (pw + q.z)  + 0.375f * (q.x + q.y);
            ring[u0][2] = 0.125f * (q.x + q.w) + 0.375f * (q.y + q.z);
            ring[u0][3] = 0.125f * (q.y + nx)  + 0.375f * (q.z + q.w);
            ringE[u0]   = 0.125f * q.z + 0.375f * q.w;   // w=128 (lane 31)

            const int ohl = r - 1 - oh0;
            if (ohl >= 0 && ohl < ohN) {                 // uniform branch
                // rows r-3..r = static slots (u+3),(u),(u+1),(u+2) &3
                const int s0 = (u + 3) & 3, s1 = u & 3, s2 = (u + 1) & 3, s3 = u0;
                const int slot = ohl & 7;
                float o0 = 0.125f * (ring[s0][0] + ring[s3][0]) + 0.375f * (ring[s1][0] + ring[s2][0]);
                float o1 = 0.125f * (ring[s0][1] + ring[s3][1]) + 0.375f * (ring[s1][1] + ring[s2][1]);
                float o2 = 0.125f * (ring[s0][2] + ring[s3][2]) + 0.375f * (ring[s1][2] + ring[s2][2]);
                float o3 = 0.125f * (ring[s0][3] + ring[s3][3]) + 0.375f * (ring[s1][3] + ring[s2][3]);
                *(__half2*)&stE[slot][c][2 * lane] = __floats2half2_rn(o0, o2);
                *(__half2*)&stO[slot][c][2 * lane] = __floats2half2_rn(o1, o3);
                if (lane == 31) {
                    float oE = 0.125f * (ringE[s0] + ringE[s3])
                             + 0.375f * (ringE[s1] + ringE[s2]);
                    stE[slot][c][64] = __float2half_rn(oE);
                }
                if ((ohl & 7) == 7 || ohl == ohN - 1) {
                    __syncthreads();
                    const int fbase = ohl & ~7;
                    const int wid = c;                   // warp = flush row
                    if (fbase + wid <= ohl) {
                        const int oh2 = oh0 + fbase + wid;
                        const size_t rowoff = ((size_t)(b * 32 + cb)) * PBLK
                                            + (size_t)oh2 * (65 * 8);
                        uint32_t* gE = (uint32_t*)(g_xE + rowoff);
                        uint32_t* gO = (uint32_t*)(g_xO + rowoff);
#pragma unroll
                        for (int t = 0; t < 2; t++) {
                            uint32_t rg[4];
                            uint32_t aE = smem_u32(&stE[wid][lane & 7][32 * t + 8 * (lane >> 3)]);
                            ldsm4t(rg, aE);
#pragma unroll
                            for (int k = 0; k < 4; k++)
                                gE[(32 * t + 8 * k + (lane >> 2)) * 4 + (lane & 3)] = rg[k];
                            uint32_t aO = smem_u32(&stO[wid][lane & 7][32 * t + 8 * (lane >> 3)]);
                            ldsm4t(rg, aO);
#pragma unroll
                            for (int k = 0; k < 4; k++)
                                gO[(32 * t + 8 * k + (lane >> 2)) * 4 + (lane & 3)] = rg[k];
                        }
                        if (lane < 8)   // w=128 edge -> E plane w2=64
                            ((__half*)gE)[64 * 8 + lane] = stE[wid][lane][64];
                    }
                    __syncthreads();
                }
            }
        }
    }
}

// ---------------------------------------------------------------------------
// Weight prep: w[3][3][CIN][COUT] fp32 -> g_w[tap][COUT][CIN] fp16, * 1/48.
// ---------------------------------------------------------------------------
__global__ void __launch_bounds__(256) wprep_kernel(const float* __restrict__ w) {
    __shared__ float t[32][33];
    const int tap = blockIdx.z, o0 = blockIdx.x * 32, cb0 = blockIdx.y * 32;
    const int tx = threadIdx.x, ty = threadIdx.y;
    const float sc = 1.0f / 48.0f;
    for (int r = ty; r < 32; r += 8)
        t[r][tx] = w[((size_t)tap * CIN + cb0 + r) * COUT + o0 + tx] * sc;
    __syncthreads();
    for (int r = ty; r < 32; r += 8)
        g_w[((size_t)tap * COUT + o0 + r) * CIN + cb0 + tx] = __float2half_rn(t[tx][r]);
}

// ---------------------------------------------------------------------------
// Stage 2: implicit GEMM via mma.sync (fp16 in, fp32 accum).
// CTA: 256 thr, tile M=128 px x N=128 oc. K=2304 in 72 chunks of 32.
// 5-stage cp.async ring, wait_group 3, one __syncthreads per chunk.
// A reads from parity planes -> unit-stride w2 -> 100% sector efficiency.
// ---------------------------------------------------------------------------
#define TSTR  40                    // fp16 elements per smem row
#define STGB  20480                 // (128 A-rows + 128 B-rows) * 80B
#define NSTG  5
#define SMEM_BYTES (NSTG * STGB)    // 102400

__global__ void __launch_bounds__(256, 2) conv_mma_kernel(
    const float* __restrict__ bias, float* __restrict__ out)
{
    extern __shared__ char smem[];
    const uint32_t sA = smem_u32(smem);
    const int tid = threadIdx.x, lane = tid & 31, wid = tid >> 5;
    const int hb  = blockIdx.x * 2;     // 2 output rows per CTA
    const int oc0 = blockIdx.y * 128;
    const int b   = blockIdx.z;
    const int wm  = (wid & 3) * 32;     // warp m offset
    const int wn  = (wid >> 2) * 64;    // warp n offset

    float acc[2][8][4];
#pragma unroll
    for (int i = 0; i < 2; i++)
#pragma unroll
        for (int j = 0; j < 8; j++)
#pragma unroll
            for (int k = 0; k < 4; k++) acc[i][j][k] = 0.f;

    // Load mapping: thread -> row r (0..127), hk = which 16-cin half.
    const int r  = tid >> 1;
    const int hk = tid & 1;
    const int oh = hb + (r >> 6), ow = r & 63;

#define ISSUE_LOADS(chunk, stg)                                                  \
    {                                                                            \
        const int tap = (chunk) >> 3, c0 = ((chunk) & 7) << 5;                   \
        const int kh = tap / 3, kw = tap - kh * 3;                               \
        const __half* gsrc = (kw & 1) ? g_xO : g_xE;                             \
        const int w2 = ow + (kw >> 1);                                           \
        const int cbb = (c0 >> 3) + hk * 2;                                      \
        const size_t a0 = ((size_t)(b * 32 + cbb)) * PBLK                        \
                        + ((size_t)(2 * oh + kh) * 65 + w2) * 8;                 \
        const size_t bo = ((size_t)(tap * COUT + oc0 + r)) * CIN + c0 + hk * 16; \
        const uint32_t d = sA + (stg) * STGB + r * 80 + hk * 32;                 \
        cp16(d, gsrc + a0);             cp16(d + 16, gsrc + a0 + PBLK);          \
        const uint32_t e = d + 10240;                                            \
        cp16(e, g_w + bo);              cp16(e + 16, g_w + bo + 8);              \
    }

    ISSUE_LOADS(0, 0); cp_commit();
    ISSUE_LOADS(1, 1); cp_commit();
    ISSUE_LOADS(2, 2); cp_commit();
    ISSUE_LOADS(3, 3); cp_commit();

    int stg = 0, wstg = 4;
    for (int i = 0; i < 72; i++) {
        cp_wait3();
        __syncthreads();
        const uint32_t base = sA + stg * STGB;

#pragma unroll
        for (int ks = 0; ks < 32; ks += 16) {
            uint32_t af[2][4], bf[4][4];
#pragma unroll
            for (int mt = 0; mt < 2; mt++) {
                uint32_t a = base + ((wm + mt * 16 + (lane & 15)) * TSTR
                                     + ks + ((lane & 16) >> 1)) * 2;
                ldsm4(af[mt], a);
            }
#pragma unroll
            for (int bt = 0; bt < 4; bt++) {
                uint32_t a = base + 10240
                           + ((wn + bt * 16 + (lane & 7) + ((lane & 16) >> 1)) * TSTR
                              + ks + (lane & 8)) * 2;
                ldsm4(bf[bt], a);
            }
#pragma unroll
            for (int mt = 0; mt < 2; mt++)
#pragma unroll
                for (int bt = 0; bt < 4; bt++)
#pragma unroll
                    for (int h = 0; h < 2; h++)
                        mma16816(acc[mt][bt * 2 + h], af[mt], &bf[bt][2 * h]);
        }
        if (i + 4 < 72) ISSUE_LOADS(i + 4, wstg);
        cp_commit();
        if (++stg == NSTG) stg = 0;
        if (++wstg == NSTG) wstg = 0;
    }
    __syncthreads();   // all warps done reading stages before smem reuse

    // Epilogue: stage [oc_local][px] fp32 in smem, then coalesced writes.
    float* so = (float*)smem;           // 128 x 132 floats = 67.6KB <= 100KB
#pragma unroll
    for (int mt = 0; mt < 2; mt++)
#pragma unroll
        for (int nt = 0; nt < 8; nt++)
#pragma unroll
            for (int k = 0; k < 4; k++) {
                int px  = wm + mt * 16 + (lane >> 2) + ((k & 2) ? 8 : 0);
                int ocl = wn + nt * 8 + (lane & 3) * 2 + (k & 1);
                so[ocl * 132 + px] = acc[mt][nt][k];
            }
    __syncthreads();

    const int ocl = tid >> 1, pxb = (tid & 1) * 64;
    const float bv = bias[oc0 + ocl];
    const float gsc = 1.41421356237309515f;
    float* dst = out + (((size_t)(b * COUT + oc0 + ocl) * 64) + hb + (tid & 1)) * 64;
#pragma unroll
    for (int j = 0; j < 64; j += 4) {
        float4 v = *(const float4*)(so + ocl * 132 + pxb + j);
        v.x = ((v.x + bv) > 0.f ? (v.x + bv) : 0.2f * (v.x + bv)) * gsc;
        v.y = ((v.y + bv) > 0.f ? (v.y + bv) : 0.2f * (v.y + bv)) * gsc;
        v.z = ((v.z + bv) > 0.f ? (v.z + bv) : 0.2f * (v.z + bv)) * gsc;
        v.w = ((v.w + bv) > 0.f ? (v.w + bv) : 0.2f * (v.w + bv)) * gsc;
        *(float4*)(dst + j) = v;
    }
}

// ---------------------------------------------------------------------------
extern "C" void kernel_launch(void* const* d_in, const int* in_sizes, int n_in,
                              void* d_out, int out_size) {
    const float* x    = (const float*)d_in[0];   // [16,256,128,128]
    const float* w    = (const float*)d_in[1];   // [3,3,256,512]
    const float* bias = (const float*)d_in[2];   // [512]
    float* out = (float*)d_out;                  // [16,512,64,64]

    cudaFuncSetAttribute(conv_mma_kernel,
                         cudaFuncAttributeMaxDynamicSharedMemorySize, SMEM_BYTES);

    blur_kernel<<<1024, dim3(32, 8)>>>(x);
    wprep_kernel<<<dim3(16, 8, 9), dim3(32, 8)>>>(w);
    conv_mma_kernel<<<dim3(32, 4, B_), 256, SMEM_BYTES>>>(bias, out);
}

// round 10
// speedup vs baseline: 1.2527x; 1.0264x over previous
#include <cuda_runtime.h>
#include <cuda_fp16.h>
#include <cstdint>

#define B_    16
#define CIN   256
#define COUT  512
#define HB2   129   // blurred H/W

// Blurred intermediate, parity-split channel-blocked:
//   g_xE[b][cb][h][w2][8c] holds w = 2*w2   (w2 = 0..64)
//   g_xO[b][cb][h][w2][8c] holds w = 2*w2+1 (w2 = 0..63; 64 unused)
#define PBLK ((size_t)HB2 * 65 * 8)   // halves per channel-block per plane
static __device__ __align__(128) __half g_xE[(size_t)B_ * 32 * PBLK];
static __device__ __align__(128) __half g_xO[(size_t)B_ * 32 * PBLK];
static __device__ __align__(128) __half g_w[9 * COUT * CIN];   // [tap][oc][cin]

// ---------------------------------------------------------------------------
__device__ __forceinline__ uint32_t smem_u32(const void* p) {
    uint32_t a;
    asm("{ .reg .u64 t; cvta.to.shared.u64 t, %1; cvt.u32.u64 %0, t; }" : "=r"(a) : "l"(p));
    return a;
}
__device__ __forceinline__ void cp16(uint32_t d, const void* s) {
    asm volatile("cp.async.cg.shared.global [%0], [%1], 16;" :: "r"(d), "l"(s));
}
__device__ __forceinline__ void cp_commit() {
    asm volatile("cp.async.commit_group;" ::: "memory");
}
__device__ __forceinline__ void cp_wait2() {
    asm volatile("cp.async.wait_group 2;" ::: "memory");
}
__device__ __forceinline__ void ldsm4(uint32_t* r, uint32_t a) {
    asm volatile("ldmatrix.sync.aligned.m8n8.x4.shared.b16 {%0,%1,%2,%3}, [%4];"
                 : "=r"(r[0]), "=r"(r[1]), "=r"(r[2]), "=r"(r[3]) : "r"(a));
}
__device__ __forceinline__ void ldsm4t(uint32_t* r, uint32_t a) {
    asm volatile("ldmatrix.sync.aligned.m8n8.x4.trans.shared.b16 {%0,%1,%2,%3}, [%4];"
                 : "=r"(r[0]), "=r"(r[1]), "=r"(r[2]), "=r"(r[3]) : "r"(a));
}
__device__ __forceinline__ void mma16816(float* c, const uint32_t* a, const uint32_t* b) {
    asm volatile(
        "mma.sync.aligned.m16n8k16.row.col.f32.f16.f16.f32 "
        "{%0,%1,%2,%3}, {%4,%5,%6,%7}, {%8,%9}, {%0,%1,%2,%3};"
        : "+f"(c[0]), "+f"(c[1]), "+f"(c[2]), "+f"(c[3])
        : "r"(a[0]), "r"(a[1]), "r"(a[2]), "r"(a[3]), "r"(b[0]), "r"(b[1]));
}

// ---------------------------------------------------------------------------
// Stage 1: separable 4x4 blur, NCHW fp32 -> parity-split blocked fp16.
// Warp = one channel over a row segment (4 segments/image). The 4 row loads
// of each unrolled group are issued up front (MLP=4). Static register ring.
// Flush via ldmatrix.x4.trans -> 128B-contiguous stores per parity plane.
// ---------------------------------------------------------------------------
__global__ void __launch_bounds__(256) blur_kernel(const float* __restrict__ x) {
    __shared__ __align__(16) __half stE[8][8][72];   // 9216 B
    __shared__ __align__(16) __half stO[8][8][72];   // 9216 B
    const int seg = blockIdx.x & 3;
    const int cb  = (blockIdx.x >> 2) & 31;
    const int b   = blockIdx.x >> 7;
    const int lane = threadIdx.x, c = threadIdx.y;
    const float* xc = x + ((size_t)(b * CIN + cb * 8 + c)) * (128 * 128);

    const int oh0 = seg * 33;
    const int ohN = (seg == 3) ? 30 : 33;    // 33+33+33+30 = 129

    float ring[4][4], ringE[4];
#pragma unroll
    for (int j = 0; j < 4; j++) {
        ringE[j] = 0.f;
#pragma unroll
        for (int k = 0; k < 4; k++) ring[j][k] = 0.f;
    }

    for (int it = 0; it < 9; it++) {
        // Batch the 4 row loads first: 4 independent LDG.128 in flight.
        float4 q4[4];
#pragma unroll
        for (int u = 0; u < 4; u++) {
            const int r = oh0 - 2 + 4 * it + u;
            q4[u] = make_float4(0.f, 0.f, 0.f, 0.f);
            if ((unsigned)r < 128u && r <= oh0 + ohN)
                q4[u] = *(const float4*)(xc + r * 128 + lane * 4);
        }
#pragma unroll
        for (int u = 0; u < 4; u++) {
            const int r = oh0 - 2 + 4 * it + u;
            if (r > oh0 + ohN) break;
            float4 q = q4[u];
            float pz = __shfl_up_sync(0xffffffffu, q.z, 1);
            float pw = __shfl_up_sync(0xffffffffu, q.w, 1);
            float nx = __shfl_down_sync(0xffffffffu, q.x, 1);
            if (lane == 0)  { pz = 0.f; pw = 0.f; }
            if (lane == 31) { nx = 0.f; }
            const int u0 = (u + 2) & 3;                  // slot for row r (static)
            ring[u0][0] = 0.125f * (pz + q.y)  + 0.375f * (pw + q.x);
            ring[u0][1] = 0.125f * (pw + q.z)  + 0.375f * (q.x + q.y);
            ring[u0][2] = 0.125f * (q.x + q.w) + 0.375f * (q.y + q.z);
            ring[u0][3] = 0.125f * (q.y + nx)  + 0.375f * (q.z + q.w);
            ringE[u0]   = 0.125f * q.z + 0.375f * q.w;   // w=128 (lane 31)

            const int ohl = r - 1 - oh0;
            if (ohl >= 0 && ohl < ohN) {                 // uniform branch
                const int s0 = (u + 3) & 3, s1 = u & 3, s2 = (u + 1) & 3, s3 = u0;
                const int slot = ohl & 7;
                float o0 = 0.125f * (ring[s0][0] + ring[s3][0]) + 0.375f * (ring[s1][0] + ring[s2][0]);
                float o1 = 0.125f * (ring[s0][1] + ring[s3][1]) + 0.375f * (ring[s1][1] + ring[s2][1]);
                float o2 = 0.125f * (ring[s0][2] + ring[s3][2]) + 0.375f * (ring[s1][2] + ring[s2][2]);
                float o3 = 0.125f * (ring[s0][3] + ring[s3][3]) + 0.375f * (ring[s1][3] + ring[s2][3]);
                *(__half2*)&stE[slot][c][2 * lane] = __floats2half2_rn(o0, o2);
                *(__half2*)&stO[slot][c][2 * lane] = __floats2half2_rn(o1, o3);
                if (lane == 31) {
                    float oE = 0.125f * (ringE[s0] + ringE[s3])
                             + 0.375f * (ringE[s1] + ringE[s2]);
                    stE[slot][c][64] = __float2half_rn(oE);
                }
                if ((ohl & 7) == 7 || ohl == ohN - 1) {
                    __syncthreads();
                    const int fbase = ohl & ~7;
                    const int wid = c;                   // warp = flush row
                    if (fbase + wid <= ohl) {
                        const int oh2 = oh0 + fbase + wid;
                        const size_t rowoff = ((size_t)(b * 32 + cb)) * PBLK
                                            + (size_t)oh2 * (65 * 8);
                        uint32_t* gE = (uint32_t*)(g_xE + rowoff);
                        uint32_t* gO = (uint32_t*)(g_xO + rowoff);
#pragma unroll
                        for (int t = 0; t < 2; t++) {
                            uint32_t rg[4];
                            uint32_t aE = smem_u32(&stE[wid][lane & 7][32 * t + 8 * (lane >> 3)]);
                            ldsm4t(rg, aE);
#pragma unroll
                            for (int k = 0; k < 4; k++)
                                gE[(32 * t + 8 * k + (lane >> 2)) * 4 + (lane & 3)] = rg[k];
                            uint32_t aO = smem_u32(&stO[wid][lane & 7][32 * t + 8 * (lane >> 3)]);
                            ldsm4t(rg, aO);
#pragma unroll
                            for (int k = 0; k < 4; k++)
                                gO[(32 * t + 8 * k + (lane >> 2)) * 4 + (lane & 3)] = rg[k];
                        }
                        if (lane < 8)   // w=128 edge -> E plane w2=64
                            ((__half*)gE)[64 * 8 + lane] = stE[wid][lane][64];
                    }
                    __syncthreads();
                }
            }
        }
    }
}

// ---------------------------------------------------------------------------
// Weight prep: w[3][3][CIN][COUT] fp32 -> g_w[tap][COUT][CIN] fp16, * 1/48.
// ---------------------------------------------------------------------------
__global__ void __launch_bounds__(256) wprep_kernel(const float* __restrict__ w) {
    __shared__ float t[32][33];
    const int tap = blockIdx.z, o0 = blockIdx.x * 32, cb0 = blockIdx.y * 32;
    const int tx = threadIdx.x, ty = threadIdx.y;
    const float sc = 1.0f / 48.0f;
    for (int r = ty; r < 32; r += 8)
        t[r][tx] = w[((size_t)tap * CIN + cb0 + r) * COUT + o0 + tx] * sc;
    __syncthreads();
    for (int r = ty; r < 32; r += 8)
        g_w[((size_t)tap * COUT + o0 + r) * CIN + cb0 + tx] = __float2half_rn(t[tx][r]);
}

// ---------------------------------------------------------------------------
// Stage 2: implicit GEMM via mma.sync (fp16 in, fp32 accum) — R5 pipeline.
// CTA: 256 thr, tile M=128 px x N=128 oc. K=2304 in 72 chunks of 32.
// 4-stage cp.async ring, STATIC (i&3) offsets, wait_group 2, one sync/chunk.
// A reads from parity planes -> contiguous 256B runs per warp.
// ---------------------------------------------------------------------------
#define TSTR  40                    // fp16 elements per smem row
#define STGB  20480                 // (128 A-rows + 128 B-rows) * 80B
#define SMEM_BYTES (4 * STGB)       // 81920

__global__ void __launch_bounds__(256, 2) conv_mma_kernel(
    const float* __restrict__ bias, float* __restrict__ out)
{
    extern __shared__ char smem[];
    const uint32_t sA = smem_u32(smem);
    const int tid = threadIdx.x, lane = tid & 31, wid = tid >> 5;
    const int hb  = blockIdx.x * 2;     // 2 output rows per CTA
    const int oc0 = blockIdx.y * 128;
    const int b   = blockIdx.z;
    const int wm  = (wid & 3) * 32;     // warp m offset
    const int wn  = (wid >> 2) * 64;    // warp n offset

    float acc[2][8][4];
#pragma unroll
    for (int i = 0; i < 2; i++)
#pragma unroll
        for (int j = 0; j < 8; j++)
#pragma unroll
            for (int k = 0; k < 4; k++) acc[i][j][k] = 0.f;

    // Load mapping: thread -> row r (0..127), hk = which 16-cin half.
    const int r  = tid >> 1;
    const int hk = tid & 1;
    const int oh = hb + (r >> 6), ow = r & 63;

#define ISSUE_LOADS(chunk, stg)                                                  \
    {                                                                            \
        const int tap = (chunk) >> 3, c0 = ((chunk) & 7) << 5;                   \
        const int kh = tap / 3, kw = tap - kh * 3;                               \
        const __half* gsrc = (kw & 1) ? g_xO : g_xE;                             \
        const int w2 = ow + (kw >> 1);                                           \
        const int cbb = (c0 >> 3) + hk * 2;                                      \
        const size_t a0 = ((size_t)(b * 32 + cbb)) * PBLK                        \
                        + ((size_t)(2 * oh + kh) * 65 + w2) * 8;                 \
        const size_t bo = ((size_t)(tap * COUT + oc0 + r)) * CIN + c0 + hk * 16; \
        const uint32_t d = sA + (stg) * STGB + r * 80 + hk * 32;                 \
        cp16(d, gsrc + a0);             cp16(d + 16, gsrc + a0 + PBLK);          \
        const uint32_t e = d + 10240;                                            \
        cp16(e, g_w + bo);              cp16(e + 16, g_w + bo + 8);              \
    }

    ISSUE_LOADS(0, 0); cp_commit();
    ISSUE_LOADS(1, 1); cp_commit();
    ISSUE_LOADS(2, 2); cp_commit();

    for (int i = 0; i < 72; i++) {
        cp_wait2();
        __syncthreads();
        const uint32_t base = sA + (i & 3) * STGB;

#pragma unroll
        for (int ks = 0; ks < 32; ks += 16) {
            uint32_t af[2][4], bf[4][4];
#pragma unroll
            for (int mt = 0; mt < 2; mt++) {
                uint32_t a = base + ((wm + mt * 16 + (lane & 15)) * TSTR
                                     + ks + ((lane & 16) >> 1)) * 2;
                ldsm4(af[mt], a);
            }
#pragma unroll
            for (int bt = 0; bt < 4; bt++) {
                uint32_t a = base + 10240
                           + ((wn + bt * 16 + (lane & 7) + ((lane & 16) >> 1)) * TSTR
                              + ks + (lane & 8)) * 2;
                ldsm4(bf[bt], a);
            }
#pragma unroll
            for (int mt = 0; mt < 2; mt++)
#pragma unroll
                for (int bt = 0; bt < 4; bt++)
#pragma unroll
                    for (int h = 0; h < 2; h++)
                        mma16816(acc[mt][bt * 2 + h], af[mt], &bf[bt][2 * h]);
        }
        if (i + 3 < 72) ISSUE_LOADS(i + 3, (i + 3) & 3);
        cp_commit();
    }
    __syncthreads();   // all warps done reading stages before smem reuse

    // Epilogue: stage [oc_local][px] fp32 in smem, then coalesced writes.
    float* so = (float*)smem;           // 128 x 132 floats = 67.6KB <= 80KB
#pragma unroll
    for (int mt = 0; mt < 2; mt++)
#pragma unroll
        for (int nt = 0; nt < 8; nt++)
#pragma unroll
            for (int k = 0; k < 4; k++) {
                int px  = wm + mt * 16 + (lane >> 2) + ((k & 2) ? 8 : 0);
                int ocl = wn + nt * 8 + (lane & 3) * 2 + (k & 1);
                so[ocl * 132 + px] = acc[mt][nt][k];
            }
    __syncthreads();

    const int ocl = tid >> 1, pxb = (tid & 1) * 64;
    const float bv = __ldg(bias + oc0 + ocl);
    const float gsc = 1.41421356237309515f;
    float* dst = out + (((size_t)(b * COUT + oc0 + ocl) * 64) + hb + (tid & 1)) * 64;
#pragma unroll
    for (int j = 0; j < 64; j += 4) {
        float4 v = *(const float4*)(so + ocl * 132 + pxb + j);
        v.x = ((v.x + bv) > 0.f ? (v.x + bv) : 0.2f * (v.x + bv)) * gsc;
        v.y = ((v.y + bv) > 0.f ? (v.y + bv) : 0.2f * (v.y + bv)) * gsc;
        v.z = ((v.z + bv) > 0.f ? (v.z + bv) : 0.2f * (v.z + bv)) * gsc;
        v.w = ((v.w + bv) > 0.f ? (v.w + bv) : 0.2f * (v.w + bv)) * gsc;
        *(float4*)(dst + j) = v;
    }
}

// ---------------------------------------------------------------------------
extern "C" void kernel_launch(void* const* d_in, const int* in_sizes, int n_in,
                              void* d_out, int out_size) {
    const float* x    = (const float*)d_in[0];   // [16,256,128,128]
    const float* w    = (const float*)d_in[1];   // [3,3,256,512]
    const float* bias = (const float*)d_in[2];   // [512]
    float* out = (float*)d_out;                  // [16,512,64,64]

    cudaFuncSetAttribute(conv_mma_kernel,
                         cudaFuncAttributeMaxDynamicSharedMemorySize, SMEM_BYTES);

    blur_kernel<<<2048, dim3(32, 8)>>>(x);
    wprep_kernel<<<dim3(16, 8, 9), dim3(32, 8)>>>(w);
    conv_mma_kernel<<<dim3(32, 4, B_), 256, SMEM_BYTES>>>(bias, out);
}

// round 11
// speedup vs baseline: 1.2626x; 1.0080x over previous
#include <cuda_runtime.h>
#include <cuda_fp16.h>
#include <cstdint>

#define B_    16
#define CIN   256
#define COUT  512
#define HB2   129   // blurred H/W

// Blurred intermediate, parity-split, 16-channel-blocked:
//   g_xE[b][c/16][h][w2][16c] holds w = 2*w2   (w2 = 0..64)
//   g_xO[b][c/16][h][w2][16c] holds w = 2*w2+1 (w2 = 0..63; 64 pad)
#define PBLK16 ((size_t)HB2 * 65 * 16)   // halves per 16ch-block per plane
static __device__ __align__(128) __half g_xE[(size_t)B_ * 16 * PBLK16];
static __device__ __align__(128) __half g_xO[(size_t)B_ * 16 * PBLK16];
static __device__ __align__(128) __half g_w[9 * COUT * CIN];   // [tap][oc][cin]

// ---------------------------------------------------------------------------
__device__ __forceinline__ uint32_t smem_u32(const void* p) {
    uint32_t a;
    asm("{ .reg .u64 t; cvta.to.shared.u64 t, %1; cvt.u32.u64 %0, t; }" : "=r"(a) : "l"(p));
    return a;
}
__device__ __forceinline__ void cp16(uint32_t d, const void* s) {
    asm volatile("cp.async.cg.shared.global [%0], [%1], 16;" :: "r"(d), "l"(s));
}
__device__ __forceinline__ void cp_commit() {
    asm volatile("cp.async.commit_group;" ::: "memory");
}
__device__ __forceinline__ void cp_wait2() {
    asm volatile("cp.async.wait_group 2;" ::: "memory");
}
__device__ __forceinline__ void ldsm4(uint32_t* r, uint32_t a) {
    asm volatile("ldmatrix.sync.aligned.m8n8.x4.shared.b16 {%0,%1,%2,%3}, [%4];"
                 : "=r"(r[0]), "=r"(r[1]), "=r"(r[2]), "=r"(r[3]) : "r"(a));
}
__device__ __forceinline__ void ldsm4t(uint32_t* r, uint32_t a) {
    asm volatile("ldmatrix.sync.aligned.m8n8.x4.trans.shared.b16 {%0,%1,%2,%3}, [%4];"
                 : "=r"(r[0]), "=r"(r[1]), "=r"(r[2]), "=r"(r[3]) : "r"(a));
}
__device__ __forceinline__ void mma16816(float* c, const uint32_t* a, const uint32_t* b) {
    asm volatile(
        "mma.sync.aligned.m16n8k16.row.col.f32.f16.f16.f32 "
        "{%0,%1,%2,%3}, {%4,%5,%6,%7}, {%8,%9}, {%0,%1,%2,%3};"
        : "+f"(c[0]), "+f"(c[1]), "+f"(c[2]), "+f"(c[3])
        : "r"(a[0]), "r"(a[1]), "r"(a[2]), "r"(a[3]), "r"(b[0]), "r"(b[1]));
}

// ---------------------------------------------------------------------------
// Stage 1: separable 4x4 blur, NCHW fp32 -> parity-split blocked-16 fp16.
// Warp = one channel over a row segment (4 segments/image), MLP=4 batched
// row loads, static register ring. Flush via ldmatrix.x4.trans; each 8-ch
// CTA writes its 16B half of every 32B pixel (L2 merges the halves).
// ---------------------------------------------------------------------------
__global__ void __launch_bounds__(256) blur_kernel(const float* __restrict__ x) {
    __shared__ __align__(16) __half stE[8][8][72];   // 9216 B
    __shared__ __align__(16) __half stO[8][8][72];   // 9216 B
    const int seg = blockIdx.x & 3;
    const int cb  = (blockIdx.x >> 2) & 31;          // 8-channel group
    const int b   = blockIdx.x >> 7;
    const int lane = threadIdx.x, c = threadIdx.y;
    const float* xc = x + ((size_t)(b * CIN + cb * 8 + c)) * (128 * 128);

    const int cb16 = cb >> 1, sub = cb & 1;          // 16-ch block, half index
    const int oh0 = seg * 33;
    const int ohN = (seg == 3) ? 30 : 33;            // 33+33+33+30 = 129

    float ring[4][4], ringE[4];
#pragma unroll
    for (int j = 0; j < 4; j++) {
        ringE[j] = 0.f;
#pragma unroll
        for (int k = 0; k < 4; k++) ring[j][k] = 0.f;
    }

    for (int it = 0; it < 9; it++) {
        float4 q4[4];
#pragma unroll
        for (int u = 0; u < 4; u++) {
            const int r = oh0 - 2 + 4 * it + u;
            q4[u] = make_float4(0.f, 0.f, 0.f, 0.f);
            if ((unsigned)r < 128u && r <= oh0 + ohN)
                q4[u] = *(const float4*)(xc + r * 128 + lane * 4);
        }
#pragma unroll
        for (int u = 0; u < 4; u++) {
            const int r = oh0 - 2 + 4 * it + u;
            if (r > oh0 + ohN) break;
            float4 q = q4[u];
            float pz = __shfl_up_sync(0xffffffffu, q.z, 1);
            float pw = __shfl_up_sync(0xffffffffu, q.w, 1);
            float nx = __shfl_down_sync(0xffffffffu, q.x, 1);
            if (lane == 0)  { pz = 0.f; pw = 0.f; }
            if (lane == 31) { nx = 0.f; }
            const int u0 = (u + 2) & 3;
            ring[u0][0] = 0.125f * (pz + q.y)  + 0.375f * (pw + q.x);
            ring[u0][1] = 0.125f * (pw + q.z)  + 0.375f * (q.x + q.y);
            ring[u0][2] = 0.125f * (q.x + q.w) + 0.375f * (q.y + q.z);
            ring[u0][3] = 0.125f * (q.y + nx)  + 0.375f * (q.z + q.w);
            ringE[u0]   = 0.125f * q.z + 0.375f * q.w;   // w=128 (lane 31)

            const int ohl = r - 1 - oh0;
            if (ohl >= 0 && ohl < ohN) {
                const int s0 = (u + 3) & 3, s1 = u & 3, s2 = (u + 1) & 3, s3 = u0;
                const int slot = ohl & 7;
                float o0 = 0.125f * (ring[s0][0] + ring[s3][0]) + 0.375f * (ring[s1][0] + ring[s2][0]);
                float o1 = 0.125f * (ring[s0][1] + ring[s3][1]) + 0.375f * (ring[s1][1] + ring[s2][1]);
                float o2 = 0.125f * (ring[s0][2] + ring[s3][2]) + 0.375f * (ring[s1][2] + ring[s2][2]);
                float o3 = 0.125f * (ring[s0][3] + ring[s3][3]) + 0.375f * (ring[s1][3] + ring[s2][3]);
                *(__half2*)&stE[slot][c][2 * lane] = __floats2half2_rn(o0, o2);
                *(__half2*)&stO[slot][c][2 * lane] = __floats2half2_rn(o1, o3);
                if (lane == 31) {
                    float oE = 0.125f * (ringE[s0] + ringE[s3])
                             + 0.375f * (ringE[s1] + ringE[s2]);
                    stE[slot][c][64] = __float2half_rn(oE);
                }
                if ((ohl & 7) == 7 || ohl == ohN - 1) {
                    __syncthreads();
                    const int fbase = ohl & ~7;
                    const int wid = c;                   // warp = flush row
                    if (fbase + wid <= ohl) {
                        const int oh2 = oh0 + fbase + wid;
                        // row base + this CTA's 16B half of each 32B pixel
                        const size_t rowoff = ((size_t)(b * 16 + cb16) * HB2 + oh2)
                                              * (65 * 16) + sub * 8;
                        uint32_t* gE = (uint32_t*)(g_xE + rowoff);
                        uint32_t* gO = (uint32_t*)(g_xO + rowoff);
#pragma unroll
                        for (int t = 0; t < 2; t++) {
                            uint32_t rg[4];
                            uint32_t aE = smem_u32(&stE[wid][lane & 7][32 * t + 8 * (lane >> 3)]);
                            ldsm4t(rg, aE);
#pragma unroll
                            for (int k = 0; k < 4; k++)
                                gE[(32 * t + 8 * k + (lane >> 2)) * 8 + (lane & 3)] = rg[k];
                            uint32_t aO = smem_u32(&stO[wid][lane & 7][32 * t + 8 * (lane >> 3)]);
                            ldsm4t(rg, aO);
#pragma unroll
                            for (int k = 0; k < 4; k++)
                                gO[(32 * t + 8 * k + (lane >> 2)) * 8 + (lane & 3)] = rg[k];
                        }
                        if (lane < 8)   // w=128 edge -> E plane w2=64
                            ((__half*)gE)[64 * 16 + lane] = stE[wid][lane][64];
                    }
                    __syncthreads();
                }
            }
        }
    }
}

// ---------------------------------------------------------------------------
// Weight prep: w[3][3][CIN][COUT] fp32 -> g_w[tap][COUT][CIN] fp16, * 1/48.
// ---------------------------------------------------------------------------
__global__ void __launch_bounds__(256) wprep_kernel(const float* __restrict__ w) {
    __shared__ float t[32][33];
    const int tap = blockIdx.z, o0 = blockIdx.x * 32, cb0 = blockIdx.y * 32;
    const int tx = threadIdx.x, ty = threadIdx.y;
    const float sc = 1.0f / 48.0f;
    for (int r = ty; r < 32; r += 8)
        t[r][tx] = w[((size_t)tap * CIN + cb0 + r) * COUT + o0 + tx] * sc;
    __syncthreads();
    for (int r = ty; r < 32; r += 8)
        g_w[((size_t)tap * COUT + o0 + r) * CIN + cb0 + tx] = __float2half_rn(t[tx][r]);
}

// ---------------------------------------------------------------------------
// Stage 2: implicit GEMM via mma.sync (fp16 in, fp32 accum).
// CTA: 256 thr, tile M=128 px x N=128 oc. K=2304 in 72 chunks of 32.
// 4-stage cp.async ring, static (i&3) offsets, wait_group 2, one sync/chunk.
// A reads: hk picks a 16-ch block -> TWO CONSECUTIVE cp16 (32B aligned),
// 512B contiguous per 16 lanes. This restores the R6-era A-load shape.
// ---------------------------------------------------------------------------
#define TSTR  40                    // fp16 elements per smem row
#define STGB  20480                 // (128 A-rows + 128 B-rows) * 80B
#define SMEM_BYTES (4 * STGB)       // 81920

__global__ void __launch_bounds__(256, 2) conv_mma_kernel(
    const float* __restrict__ bias, float* __restrict__ out)
{
    extern __shared__ char smem[];
    const uint32_t sA = smem_u32(smem);
    const int tid = threadIdx.x, lane = tid & 31, wid = tid >> 5;
    const int hb  = blockIdx.x * 2;     // 2 output rows per CTA
    const int oc0 = blockIdx.y * 128;
    const int b   = blockIdx.z;
    const int wm  = (wid & 3) * 32;     // warp m offset
    const int wn  = (wid >> 2) * 64;    // warp n offset

    float acc[2][8][4];
#pragma unroll
    for (int i = 0; i < 2; i++)
#pragma unroll
        for (int j = 0; j < 8; j++)
#pragma unroll
            for (int k = 0; k < 4; k++) acc[i][j][k] = 0.f;

    // Load mapping: thread -> row r (0..127), hk = which 16-cin block.
    const int r  = tid >> 1;
    const int hk = tid & 1;
    const int oh = hb + (r >> 6), ow = r & 63;

#define ISSUE_LOADS(chunk, stg)                                                  \
    {                                                                            \
        const int tap = (chunk) >> 3, c0 = ((chunk) & 7) << 5;                   \
        const int kh = tap / 3, kw = tap - kh * 3;                               \
        const __half* gsrc = (kw & 1) ? g_xO : g_xE;                             \
        const int w2 = ow + (kw >> 1);                                           \
        const int cbb = (c0 >> 4) + hk;                                          \
        const size_t a0 = ((size_t)(b * 16 + cbb) * HB2 + (2 * oh + kh))         \
                          * (65 * 16) + (size_t)w2 * 16;                         \
        const size_t bo = ((size_t)(tap * COUT + oc0 + r)) * CIN + c0 + hk * 16; \
        const uint32_t d = sA + (stg) * STGB + r * 80 + hk * 32;                 \
        cp16(d, gsrc + a0);             cp16(d + 16, gsrc + a0 + 8);             \
        const uint32_t e = d + 10240;                                            \
        cp16(e, g_w + bo);              cp16(e + 16, g_w + bo + 8);              \
    }

    ISSUE_LOADS(0, 0); cp_commit();
    ISSUE_LOADS(1, 1); cp_commit();
    ISSUE_LOADS(2, 2); cp_commit();

    for (int i = 0; i < 72; i++) {
        cp_wait2();
        __syncthreads();
        const uint32_t base = sA + (i & 3) * STGB;

#pragma unroll
        for (int ks = 0; ks < 32; ks += 16) {
            uint32_t af[2][4], bf[4][4];
#pragma unroll
            for (int mt = 0; mt < 2; mt++) {
                uint32_t a = base + ((wm + mt * 16 + (lane & 15)) * TSTR
                                     + ks + ((lane & 16) >> 1)) * 2;
                ldsm4(af[mt], a);
            }
#pragma unroll
            for (int bt = 0; bt < 4; bt++) {
                uint32_t a = base + 10240
                           + ((wn + bt * 16 + (lane & 7) + ((lane & 16) >> 1)) * TSTR
                              + ks + (lane & 8)) * 2;
                ldsm4(bf[bt], a);
            }
#pragma unroll
            for (int mt = 0; mt < 2; mt++)
#pragma unroll
                for (int bt = 0; bt < 4; bt++)
#pragma unroll
                    for (int h = 0; h < 2; h++)
                        mma16816(acc[mt][bt * 2 + h], af[mt], &bf[bt][2 * h]);
        }
        if (i + 3 < 72) ISSUE_LOADS(i + 3, (i + 3) & 3);
        cp_commit();
    }
    __syncthreads();   // all warps done reading stages before smem reuse

    // Epilogue: stage [oc_local][px] fp32 in smem, then coalesced writes.
    float* so = (float*)smem;           // 128 x 132 floats = 67.6KB <= 80KB
#pragma unroll
    for (int mt = 0; mt < 2; mt++)
#pragma unroll
        for (int nt = 0; nt < 8; nt++)
#pragma unroll
            for (int k = 0; k < 4; k++) {
                int px  = wm + mt * 16 + (lane >> 2) + ((k & 2) ? 8 : 0);
                int ocl = wn + nt * 8 + (lane & 3) * 2 + (k & 1);
                so[ocl * 132 + px] = acc[mt][nt][k];
            }
    __syncthreads();

    const int ocl = tid >> 1, pxb = (tid & 1) * 64;
    const float bv = bias[oc0 + ocl];
    const float gsc = 1.41421356237309515f;
    float* dst = out + (((size_t)(b * COUT + oc0 + ocl) * 64) + hb + (tid & 1)) * 64;
#pragma unroll
    for (int j = 0; j < 64; j += 4) {
        float4 v = *(const float4*)(so + ocl * 132 + pxb + j);
        v.x = ((v.x + bv) > 0.f ? (v.x + bv) : 0.2f * (v.x + bv)) * gsc;
        v.y = ((v.y + bv) > 0.f ? (v.y + bv) : 0.2f * (v.y + bv)) * gsc;
        v.z = ((v.z + bv) > 0.f ? (v.z + bv) : 0.2f * (v.z + bv)) * gsc;
        v.w = ((v.w + bv) > 0.f ? (v.w + bv) : 0.2f * (v.w + bv)) * gsc;
        *(float4*)(dst + j) = v;
    }
}

// ---------------------------------------------------------------------------
extern "C" void kernel_launch(void* const* d_in, const int* in_sizes, int n_in,
                              void* d_out, int out_size) {
    const float* x    = (const float*)d_in[0];   // [16,256,128,128]
    const float* w    = (const float*)d_in[1];   // [3,3,256,512]
    const float* bias = (const float*)d_in[2];   // [512]
    float* out = (float*)d_out;                  // [16,512,64,64]

    cudaFuncSetAttribute(conv_mma_kernel,
                         cudaFuncAttributeMaxDynamicSharedMemorySize, SMEM_BYTES);

    blur_kernel<<<2048, dim3(32, 8)>>>(x);
    wprep_kernel<<<dim3(16, 8, 9), dim3(32, 8)>>>(w);
    conv_mma_kernel<<<dim3(32, 4, B_), 256, SMEM_BYTES>>>(bias, out);
}

// round 12
// speedup vs baseline: 1.4099x; 1.1166x over previous
#include <cuda_runtime.h>
#include <cuda_fp16.h>
#include <cstdint>

#define B_    16
#define CIN   256
#define COUT  512
#define HB2   129   // blurred H/W

// Blurred intermediate NHWC-256 fp16; weights [tap][oc][cin] fp16.
static __device__ __align__(128) __half g_x[(size_t)B_ * HB2 * HB2 * CIN];
static __device__ __align__(128) __half g_w[9 * COUT * CIN];

// ---------------------------------------------------------------------------
__device__ __forceinline__ uint32_t smem_u32(const void* p) {
    uint32_t a;
    asm("{ .reg .u64 t; cvta.to.shared.u64 t, %1; cvt.u32.u64 %0, t; }" : "=r"(a) : "l"(p));
    return a;
}
__device__ __forceinline__ void cp16(uint32_t d, const void* s) {
    asm volatile("cp.async.cg.shared.global [%0], [%1], 16;" :: "r"(d), "l"(s));
}
__device__ __forceinline__ void cp_commit() {
    asm volatile("cp.async.commit_group;" ::: "memory");
}
__device__ __forceinline__ void cp_wait2() {
    asm volatile("cp.async.wait_group 2;" ::: "memory");
}
__device__ __forceinline__ void ldsm4(uint32_t* r, uint32_t a) {
    asm volatile("ldmatrix.sync.aligned.m8n8.x4.shared.b16 {%0,%1,%2,%3}, [%4];"
                 : "=r"(r[0]), "=r"(r[1]), "=r"(r[2]), "=r"(r[3]) : "r"(a));
}
__device__ __forceinline__ void ldsm4t(uint32_t* r, uint32_t a) {
    asm volatile("ldmatrix.sync.aligned.m8n8.x4.trans.shared.b16 {%0,%1,%2,%3}, [%4];"
                 : "=r"(r[0]), "=r"(r[1]), "=r"(r[2]), "=r"(r[3]) : "r"(a));
}
__device__ __forceinline__ void mma16816(float* c, const uint32_t* a, const uint32_t* b) {
    asm volatile(
        "mma.sync.aligned.m16n8k16.row.col.f32.f16.f16.f32 "
        "{%0,%1,%2,%3}, {%4,%5,%6,%7}, {%8,%9}, {%0,%1,%2,%3};"
        : "+f"(c[0]), "+f"(c[1]), "+f"(c[2]), "+f"(c[3])
        : "r"(a[0]), "r"(a[1]), "r"(a[2]), "r"(a[3]), "r"(b[0]), "r"(b[1]));
}

// ---------------------------------------------------------------------------
// Stage 1: separable 4x4 blur, NCHW fp32 -> NHWC-256 fp16.
// Warp = one channel over a row segment (4/image), MLP=4 batched loads,
// static register ring. Stage: [slot][8c][136] channel-major; flush via
// ldmatrix.x4.trans -> each lane stores 4B words of the CTA's 16B piece
// of each 512B NHWC pixel.
// ---------------------------------------------------------------------------
__global__ void __launch_bounds__(256) blur_kernel(const float* __restrict__ x) {
    __shared__ __align__(16) __half st[8][8][136];   // 17408 B
    const int seg = blockIdx.x & 3;
    const int cb  = (blockIdx.x >> 2) & 31;          // 8-channel group
    const int b   = blockIdx.x >> 7;
    const int lane = threadIdx.x, c = threadIdx.y;
    const float* xc = x + ((size_t)(b * CIN + cb * 8 + c)) * (128 * 128);

    const int oh0 = seg * 33;
    const int ohN = (seg == 3) ? 30 : 33;            // 33+33+33+30 = 129

    float ring[4][4], ringE[4];
#pragma unroll
    for (int j = 0; j < 4; j++) {
        ringE[j] = 0.f;
#pragma unroll
        for (int k = 0; k < 4; k++) ring[j][k] = 0.f;
    }

    for (int it = 0; it < 9; it++) {
        float4 q4[4];
#pragma unroll
        for (int u = 0; u < 4; u++) {
            const int r = oh0 - 2 + 4 * it + u;
            q4[u] = make_float4(0.f, 0.f, 0.f, 0.f);
            if ((unsigned)r < 128u && r <= oh0 + ohN)
                q4[u] = *(const float4*)(xc + r * 128 + lane * 4);
        }
#pragma unroll
        for (int u = 0; u < 4; u++) {
            const int r = oh0 - 2 + 4 * it + u;
            if (r > oh0 + ohN) break;
            float4 q = q4[u];
            float pz = __shfl_up_sync(0xffffffffu, q.z, 1);
            float pw = __shfl_up_sync(0xffffffffu, q.w, 1);
            float nx = __shfl_down_sync(0xffffffffu, q.x, 1);
            if (lane == 0)  { pz = 0.f; pw = 0.f; }
            if (lane == 31) { nx = 0.f; }
            const int u0 = (u + 2) & 3;                  // slot for row r (static)
            ring[u0][0] = 0.125f * (pz + q.y)  + 0.375f * (pw + q.x);
            ring[u0][1] = 0.125f * (pw + q.z)  + 0.375f * (q.x + q.y);
            ring[u0][2] = 0.125f * (q.x + q.w) + 0.375f * (q.y + q.z);
            ring[u0][3] = 0.125f * (q.y + nx)  + 0.375f * (q.z + q.w);
            ringE[u0]   = 0.125f * q.z + 0.375f * q.w;   // w=128 (lane 31)

            const int ohl = r - 1 - oh0;
            if (ohl >= 0 && ohl < ohN) {
                const int s0 = (u + 3) & 3, s1 = u & 3, s2 = (u + 1) & 3, s3 = u0;
                const int slot = ohl & 7;
                float o0 = 0.125f * (ring[s0][0] + ring[s3][0]) + 0.375f * (ring[s1][0] + ring[s2][0]);
                float o1 = 0.125f * (ring[s0][1] + ring[s3][1]) + 0.375f * (ring[s1][1] + ring[s2][1]);
                float o2 = 0.125f * (ring[s0][2] + ring[s3][2]) + 0.375f * (ring[s1][2] + ring[s2][2]);
                float o3 = 0.125f * (ring[s0][3] + ring[s3][3]) + 0.375f * (ring[s1][3] + ring[s2][3]);
                *(__half2*)&st[slot][c][4 * lane]     = __floats2half2_rn(o0, o1);
                *(__half2*)&st[slot][c][4 * lane + 2] = __floats2half2_rn(o2, o3);
                if (lane == 31) {
                    float oE = 0.125f * (ringE[s0] + ringE[s3])
                             + 0.375f * (ringE[s1] + ringE[s2]);
                    st[slot][c][128] = __float2half_rn(oE);
                }
                if ((ohl & 7) == 7 || ohl == ohN - 1) {
                    __syncthreads();
                    const int fbase = ohl & ~7;
                    const int wid = c;                   // warp = flush row
                    if (fbase + wid <= ohl) {
                        const int oh2 = oh0 + fbase + wid;
                        // NHWC pixel base (uint32 words): pixel*128 + cb*4
                        uint32_t* gw = (uint32_t*)(g_x
                            + ((size_t)(b * HB2 + oh2)) * HB2 * CIN) + cb * 4;
#pragma unroll
                        for (int t = 0; t < 4; t++) {
                            uint32_t rg[4];
                            uint32_t a = smem_u32(&st[wid][lane & 7][32 * t + 8 * (lane >> 3)]);
                            ldsm4t(rg, a);
#pragma unroll
                            for (int k = 0; k < 4; k++)
                                gw[(32 * t + 8 * k + (lane >> 2)) * 128 + (lane & 3)] = rg[k];
                        }
                        if (lane < 8)   // w = 128 edge
                            ((__half*)gw)[128 * 256 + lane] = st[wid][lane][128];
                    }
                    __syncthreads();
                }
            }
        }
    }
}

// ---------------------------------------------------------------------------
// Weight prep: w[3][3][CIN][COUT] fp32 -> g_w[tap][COUT][CIN] fp16, * 1/48.
// ---------------------------------------------------------------------------
__global__ void __launch_bounds__(256) wprep_kernel(const float* __restrict__ w) {
    __shared__ float t[32][33];
    const int tap = blockIdx.z, o0 = blockIdx.x * 32, cb0 = blockIdx.y * 32;
    const int tx = threadIdx.x, ty = threadIdx.y;
    const float sc = 1.0f / 48.0f;
    for (int r = ty; r < 32; r += 8)
        t[r][tx] = w[((size_t)tap * CIN + cb0 + r) * COUT + o0 + tx] * sc;
    __syncthreads();
    for (int r = ty; r < 32; r += 8)
        g_w[((size_t)tap * COUT + o0 + r) * CIN + cb0 + tx] = __float2half_rn(t[tx][r]);
}

// ---------------------------------------------------------------------------
// Stage 2: implicit GEMM via mma.sync (fp16 in, fp32 accum).
// EXACT known-good config: CTA 256 thr, tile M=128 x N=128, K=2304 in 72
// chunks of 32, 4-stage cp.async ring, static (i&3), wait_group 2, one
// sync/chunk, NHWC-256 A loads, TSTR 40, 81920 B smem, 2 CTAs/SM.
// ---------------------------------------------------------------------------
#define TSTR  40                    // fp16 elements per smem row
#define STGB  20480                 // (128 A-rows + 128 B-rows) * 80B
#define SMEM_BYTES (4 * STGB)       // 81920

__global__ void __launch_bounds__(256, 2) conv_mma_kernel(
    const float* __restrict__ bias, float* __restrict__ out)
{
    extern __shared__ char smem[];
    const uint32_t sA = smem_u32(smem);
    const int tid = threadIdx.x, lane = tid & 31, wid = tid >> 5;
    const int hb  = blockIdx.x * 2;     // 2 output rows per CTA
    const int oc0 = blockIdx.y * 128;
    const int b   = blockIdx.z;
    const int wm  = (wid & 3) * 32;     // warp m offset
    const int wn  = (wid >> 2) * 64;    // warp n offset

    float acc[2][8][4];
#pragma unroll
    for (int i = 0; i < 2; i++)
#pragma unroll
        for (int j = 0; j < 8; j++)
#pragma unroll
            for (int k = 0; k < 4; k++) acc[i][j][k] = 0.f;

    // Load mapping: thread -> row r (0..127), hk = which 16-cin half.
    const int r  = tid >> 1;
    const int hk = tid & 1;
    const int oh = hb + (r >> 6), ow = r & 63;

#define ISSUE_LOADS(chunk, stg)                                                  \
    {                                                                            \
        const int tap = (chunk) >> 3, c0 = ((chunk) & 7) << 5;                   \
        const int kh = tap / 3, kw = tap - kh * 3;                               \
        const size_t ao = (((size_t)(b * HB2 + 2 * oh + kh)) * HB2               \
                           + (2 * ow + kw)) * CIN + c0 + hk * 16;                \
        const size_t bo = ((size_t)(tap * COUT + oc0 + r)) * CIN + c0 + hk * 16; \
        const uint32_t d = sA + (stg) * STGB + r * 80 + hk * 32;                 \
        cp16(d, g_x + ao);              cp16(d + 16, g_x + ao + 8);              \
        const uint32_t e = d + 10240;                                            \
        cp16(e, g_w + bo);              cp16(e + 16, g_w + bo + 8);              \
    }

    ISSUE_LOADS(0, 0); cp_commit();
    ISSUE_LOADS(1, 1); cp_commit();
    ISSUE_LOADS(2, 2); cp_commit();

    for (int i = 0; i < 72; i++) {
        cp_wait2();
        __syncthreads();
        const uint32_t base = sA + (i & 3) * STGB;

#pragma unroll
        for (int ks = 0; ks < 32; ks += 16) {
            uint32_t af[2][4], bf[4][4];
#pragma unroll
            for (int mt = 0; mt < 2; mt++) {
                uint32_t a = base + ((wm + mt * 16 + (lane & 15)) * TSTR
                                     + ks + ((lane & 16) >> 1)) * 2;
                ldsm4(af[mt], a);
            }
#pragma unroll
            for (int bt = 0; bt < 4; bt++) {
                uint32_t a = base + 10240
                           + ((wn + bt * 16 + (lane & 7) + ((lane & 16) >> 1)) * TSTR
                              + ks + (lane & 8)) * 2;
                ldsm4(bf[bt], a);
            }
#pragma unroll
            for (int mt = 0; mt < 2; mt++)
#pragma unroll
                for (int bt = 0; bt < 4; bt++)
#pragma unroll
                    for (int h = 0; h < 2; h++)
                        mma16816(acc[mt][bt * 2 + h], af[mt], &bf[bt][2 * h]);
        }
        if (i + 3 < 72) ISSUE_LOADS(i + 3, (i + 3) & 3);
        cp_commit();
    }
    __syncthreads();   // all warps done reading stages before smem reuse

    // Epilogue: stage [oc_local][px] fp32 in smem, then coalesced writes.
    float* so = (float*)smem;           // 128 x 132 floats = 67.6KB <= 80KB
#pragma unroll
    for (int mt = 0; mt < 2; mt++)
#pragma unroll
        for (int nt = 0; nt < 8; nt++)
#pragma unroll
            for (int k = 0; k < 4; k++) {
                int px  = wm + mt * 16 + (lane >> 2) + ((k & 2) ? 8 : 0);
                int ocl = wn + nt * 8 + (lane & 3) * 2 + (k & 1);
                so[ocl * 132 + px] = acc[mt][nt][k];
            }
    __syncthreads();

    const int ocl = tid >> 1, pxb = (tid & 1) * 64;
    const float bv = bias[oc0 + ocl];
    const float gsc = 1.41421356237309515f;
    float* dst = out + (((size_t)(b * COUT + oc0 + ocl) * 64) + hb + (tid & 1)) * 64;
#pragma unroll
    for (int j = 0; j < 64; j += 4) {
        float4 v = *(const float4*)(so + ocl * 132 + pxb + j);
        v.x = ((v.x + bv) > 0.f ? (v.x + bv) : 0.2f * (v.x + bv)) * gsc;
        v.y = ((v.y + bv) > 0.f ? (v.y + bv) : 0.2f * (v.y + bv)) * gsc;
        v.z = ((v.z + bv) > 0.f ? (v.z + bv) : 0.2f * (v.z + bv)) * gsc;
        v.w = ((v.w + bv) > 0.f ? (v.w + bv) : 0.2f * (v.w + bv)) * gsc;
        *(float4*)(dst + j) = v;
    }
}

// ---------------------------------------------------------------------------
extern "C" void kernel_launch(void* const* d_in, const int* in_sizes, int n_in,
                              void* d_out, int out_size) {
    const float* x    = (const float*)d_in[0];   // [16,256,128,128]
    const float* w    = (const float*)d_in[1];   // [3,3,256,512]
    const float* bias = (const float*)d_in[2];   // [512]
    float* out = (float*)d_out;                  // [16,512,64,64]

    cudaFuncSetAttribute(conv_mma_kernel,
                         cudaFuncAttributeMaxDynamicSharedMemorySize, SMEM_BYTES);

    blur_kernel<<<2048, dim3(32, 8)>>>(x);
    wprep_kernel<<<dim3(16, 8, 9), dim3(32, 8)>>>(w);
    conv_mma_kernel<<<dim3(32, 4, B_), 256, SMEM_BYTES>>>(bias, out);
}